// round 13
// baseline (speedup 1.0000x reference)
#include <cuda_runtime.h>
#include <cuda_fp16.h>
#include <cuda_bf16.h>
#include <math.h>
#include <stdint.h>

#define V 50257
#define D 128
#define B 1024
#define C 10
#define TWO_D 256
#define NB 2                 // batch rows per encoder CTA (512 CTAs)
#define NROW (NB * C)        // 20 cx rows per CTA

// vocab GEMM tiling (fp16 mma.sync m16n8k16)
#define M_CTA 128
#define N_CTA 128
#define KT 32
#define WS_STRIDE 136
#define WS_BUF (16 * WS_STRIDE)
#define NCHUNK ((V + N_CTA - 1) / N_CTA)   // 393
#define FIN_BLOCKS (B / 4)

// encoder smem layout (floats)
#define EO_A      0            // A_s   [20*128] = 2560
#define EO_CE     2560         // ce_s  [2*128]  = 256
#define EO_CP     2816         // cepart[2*256]  = 512
#define EO_B      3328         // B_s   [16*256] = 4096 (main loop) -> ends 7424
#define EO_HW     3328         // hw_s  [8*128]  = 1024 (post, aliases B)
#define EO_H      4352         // h_s   [2*256]  = 512  (post, aliases B)
#define EO_MEAN   0            // mean_s[2*128]  = 256  (post, aliases A)
#define EO_VAR    256          // var_s [2*128]  = 256  (post, aliases A)
#define EO_TOTAL  7424

// ---------------- scratch ----------------
__device__ float              g_z[B * D];
__device__ unsigned           g_zh2[B * D / 2];
__device__ float              g_kl[B];
__device__ float              g_pmax[B * NCHUNK];
__device__ float              g_psum[B * NCHUNK];
__device__ long long          g_acc;
__device__ unsigned int       g_done;

__device__ __forceinline__ float softplus_f(float x) {
    return fmaxf(x, 0.f) + log1pf(expf(-fabsf(x)));
}

__device__ __forceinline__ void mma_f16(float c[4],
                                        unsigned a0, unsigned a1, unsigned a2, unsigned a3,
                                        unsigned b0, unsigned b1) {
    asm volatile(
        "mma.sync.aligned.m16n8k16.row.col.f32.f16.f16.f32 "
        "{%0,%1,%2,%3}, {%4,%5,%6,%7}, {%8,%9}, {%0,%1,%2,%3};"
        : "+f"(c[0]), "+f"(c[1]), "+f"(c[2]), "+f"(c[3])
        : "r"(a0), "r"(a1), "r"(a2), "r"(a3), "r"(b0), "r"(b1));
}

// ---------------- kernel 1: register-tiled encoder (NB=2) + heads + KL + z -------
// cx GEMM [20,128]@[128,256]: 8 warps = 4 row-groups x 2 col-halves;
// warp w: rg = w>>1 (5 rows), ch = w&1 (128 cols); thread = 5 rows x 4 cols.
__global__ void __launch_bounds__(256) encoder_kernel(
    const int* __restrict__ center_id, const int* __restrict__ context_ids,
    const float* __restrict__ epsilon, const float* __restrict__ emb,
    const float* __restrict__ prior_means, const float* __restrict__ prior_vars,
    const float* __restrict__ W_enc, const float* __restrict__ b_enc,
    const float* __restrict__ W_mean, const float* __restrict__ b_mean,
    const float* __restrict__ W_var, const float* __restrict__ b_var)
{
    __shared__ float S[EO_TOTAL];
    __shared__ int   ctx_s[NROW];
    __shared__ int   cid_s[NB];
    __shared__ float red_s[NB][4];

    const int b0   = blockIdx.x * NB;
    const int tid  = threadIdx.x;
    const int lane = tid & 31;
    const int w    = tid >> 5;
    const int rg   = w >> 1;          // row group (5 rows)
    const int ch   = w & 1;           // column half (128 cols)
    const int l4   = lane * 4;

    if (blockIdx.x == 0 && tid == 0) { g_acc = 0ll; g_done = 0u; }

    if (tid < NB)   cid_s[tid] = center_id[b0 + tid];
    if (tid < NROW) ctx_s[tid] = context_ids[b0 * C + tid];
    __syncthreads();

    // gather ce (2x128) and A = cx (20x128), float4-coalesced
    if (tid < NB * 32) {
        int row = tid >> 5, l = tid & 31;
        *(float4*)&S[EO_CE + row * D + l * 4] =
            *(const float4*)&emb[cid_s[row] * D + l * 4];
    }
    for (int e = tid; e < NROW * 32; e += 256) {
        int row = e >> 5, l = e & 31;
        *(float4*)&S[EO_A + row * D + l * 4] =
            *(const float4*)&emb[ctx_s[row] * D + l * 4];
    }
    __syncthreads();

    // cepart[nb][j] = ce_nb . W1[:,j]   (j = tid)
    {
        const int j = tid;
        float cp[NB] = {0.f, 0.f};
        #pragma unroll 4
        for (int k = 0; k < D; k++) {
            float w1 = W_enc[k * TWO_D + j];
            #pragma unroll
            for (int nb = 0; nb < NB; nb++)
                cp[nb] = fmaf(S[EO_CE + nb * D + k], w1, cp[nb]);
        }
        #pragma unroll
        for (int nb = 0; nb < NB; nb++) S[EO_CP + nb * TWO_D + j] = cp[nb];
    }

    // ---- main cx GEMM, W2 staged in 16-k tiles, register prefetch ----
    float acc[5][4];
    #pragma unroll
    for (int i = 0; i < 5; i++)
        #pragma unroll
        for (int j = 0; j < 4; j++) acc[i][j] = 0.f;

    const float* W2 = W_enc + D * TWO_D;
    float4 pf[4];
    #pragma unroll
    for (int i = 0; i < 4; i++)
        pf[i] = *(const float4*)(W2 + tid * 4 + i * 1024);

    const int arow = rg * 5 * D;
    const int bcol = ch * 128 + l4;
    #pragma unroll 1
    for (int kt = 0; kt < 8; kt++) {
        __syncthreads();                       // B_s readers from prev iter done
        #pragma unroll
        for (int i = 0; i < 4; i++)
            *(float4*)&S[EO_B + tid * 4 + i * 1024] = pf[i];
        __syncthreads();
        if (kt < 7) {
            #pragma unroll
            for (int i = 0; i < 4; i++)
                pf[i] = *(const float4*)(W2 + (kt + 1) * 4096 + tid * 4 + i * 1024);
        }
        const int kb = kt * 16;
        #pragma unroll
        for (int kk = 0; kk < 16; kk++) {
            float4 bv = *(float4*)&S[EO_B + kk * TWO_D + bcol];
            #pragma unroll
            for (int i = 0; i < 5; i++) {
                float a = S[EO_A + arow + i * D + kb + kk];
                acc[i][0] = fmaf(a, bv.x, acc[i][0]);
                acc[i][1] = fmaf(a, bv.y, acc[i][1]);
                acc[i][2] = fmaf(a, bv.z, acc[i][2]);
                acc[i][3] = fmaf(a, bv.w, acc[i][3]);
            }
        }
    }
    __syncthreads();    // all B_s reads done before hw_s (aliased) writes

    // ---- epilogue: relu(acc + cepart + b_enc), sum over 5 rows -> warp partial ----
    {
        const int nb = rg >> 1;               // rows 0-9 -> nb0, 10-19 -> nb1
        float4 cp = *(float4*)&S[EO_CP + nb * TWO_D + bcol];
        float4 be = *(const float4*)&b_enc[bcol];
        float hp0 = 0.f, hp1 = 0.f, hp2 = 0.f, hp3 = 0.f;
        #pragma unroll
        for (int i = 0; i < 5; i++) {
            hp0 += fmaxf(acc[i][0] + cp.x + be.x, 0.f);
            hp1 += fmaxf(acc[i][1] + cp.y + be.y, 0.f);
            hp2 += fmaxf(acc[i][2] + cp.z + be.z, 0.f);
            hp3 += fmaxf(acc[i][3] + cp.w + be.w, 0.f);
        }
        *(float4*)&S[EO_HW + w * 128 + l4] = make_float4(hp0, hp1, hp2, hp3);
    }
    __syncthreads();
    // combine the 2 row-groups per (nb, col): h[nb][j] for j in [0,256)
    for (int e = tid; e < NB * TWO_D; e += 256) {
        int nb = e >> 8, j = e & 255;
        int jc = j & 127, jch = j >> 7;
        S[EO_H + e] = S[EO_HW + (4 * nb + jch) * 128 + jc]
                    + S[EO_HW + (4 * nb + 2 + jch) * 128 + jc];
    }
    __syncthreads();

    // ---- heads: mean (threads 0..127), softplus(var) (threads 128..255) ----
    if (tid < D) {
        int d = tid;
        float m[NB];
        #pragma unroll
        for (int nb = 0; nb < NB; nb++) m[nb] = b_mean[d];
        #pragma unroll 2
        for (int k = 0; k < TWO_D; k++) {
            float wm = W_mean[k * D + d];
            #pragma unroll
            for (int nb = 0; nb < NB; nb++)
                m[nb] = fmaf(S[EO_H + nb * TWO_D + k], wm, m[nb]);
        }
        #pragma unroll
        for (int nb = 0; nb < NB; nb++) S[EO_MEAN + nb * D + d] = m[nb];
    } else {
        int d = tid - D;
        float vr[NB];
        #pragma unroll
        for (int nb = 0; nb < NB; nb++) vr[nb] = b_var[d];
        #pragma unroll 2
        for (int k = 0; k < TWO_D; k++) {
            float wv = W_var[k * D + d];
            #pragma unroll
            for (int nb = 0; nb < NB; nb++)
                vr[nb] = fmaf(S[EO_H + nb * TWO_D + k], wv, vr[nb]);
        }
        #pragma unroll
        for (int nb = 0; nb < NB; nb++) S[EO_VAR + nb * D + d] = softplus_f(vr[nb]);
    }
    __syncthreads();

    // ---- z, KL ----
    float term[NB];
    #pragma unroll
    for (int nb = 0; nb < NB; nb++) term[nb] = 0.f;
    if (tid < D) {
        int d = tid;
        float eps = epsilon[d];
        #pragma unroll
        for (int nb = 0; nb < NB; nb++) {
            int b = b0 + nb;
            float m = S[EO_MEAN + nb * D + d];
            float v = S[EO_VAR + nb * D + d];
            float z = m + expf(0.5f * v) * eps;
            g_z[b * D + d] = z;
            float zn = __shfl_down_sync(0xffffffffu, z, 1);
            if (!(d & 1)) {
                __half2 hz = __floats2half2_rn(z, zn);
                g_zh2[(b * D + d) >> 1] = *(unsigned*)&hz;
            }
            float pm = prior_means[cid_s[nb] * D + d];
            float pv = softplus_f(prior_vars[cid_s[nb] * D + d]);
            float diff = pm - m;
            term[nb] = v / pv + diff * diff / pv - 1.f + logf(pv) - logf(v);
        }
    }
    #pragma unroll
    for (int nb = 0; nb < NB; nb++) {
        float t = term[nb];
        #pragma unroll
        for (int o = 16; o; o >>= 1) t += __shfl_xor_sync(0xffffffffu, t, o);
        if (tid < D && (tid & 31) == 0) red_s[nb][tid >> 5] = t;
    }
    __syncthreads();
    if (tid < NB) {
        float s = red_s[tid][0] + red_s[tid][1] + red_s[tid][2] + red_s[tid][3];
        g_kl[b0 + tid] = 0.5f * s;
    }
}

// ---------------- kernel 2: fp16 mma.sync vocab GEMM + fused softmax partials ----
__global__ void __launch_bounds__(256, 2) vocab_kernel(
    const float* __restrict__ Wv, const float* __restrict__ bvoc)
{
    __shared__ unsigned Ws[2 * WS_BUF];

    const int tid  = threadIdx.x;
    const int lane = tid & 31;
    const int w    = tid >> 5;
    const int g    = lane >> 2;
    const int cg   = lane & 3;
    const int v0   = blockIdx.x * N_CTA;
    const int b0   = blockIdx.y * M_CTA;

    const unsigned* zh0 = g_zh2 + (b0 + w * 16 + g) * (D / 2);
    const unsigned* zh1 = zh0 + 8 * (D / 2);

    const int n_f  = tid & 127;
    const int k2b  = tid >> 7;
    const int vf   = v0 + n_f;
    const bool okf = (vf < V);
    const float* wp = Wv + (okf ? vf : 0);

    float acc[16][4];
    #pragma unroll
    for (int t = 0; t < 16; t++)
        #pragma unroll
        for (int i = 0; i < 4; i++) acc[t][i] = 0.f;

    float plo[8], phi[8];
    #define LOADREGS(K0) do {                                                 \
        _Pragma("unroll")                                                     \
        for (int i = 0; i < 8; i++) {                                         \
            int kk = (K0) + 2 * (k2b + 2 * i);                                \
            plo[i] = okf ? wp[kk * V] : 0.f;                                  \
            phi[i] = okf ? wp[(kk + 1) * V] : 0.f;                            \
        } } while (0)
    #define STOREREGS(BUF) do {                                               \
        _Pragma("unroll")                                                     \
        for (int i = 0; i < 8; i++) {                                         \
            __half2 hv = __floats2half2_rn(plo[i], phi[i]);                   \
            (BUF)[(k2b + 2 * i) * WS_STRIDE + n_f] = *(unsigned*)&hv;         \
        } } while (0)

    LOADREGS(0);
    #pragma unroll
    for (int it = 0; it < 4; it++) {
        unsigned* buf = Ws + (it & 1) * WS_BUF;
        STOREREGS(buf);
        __syncthreads();
        if (it < 3) LOADREGS((it + 1) * KT);

        const int k0 = it * KT;
        #pragma unroll
        for (int ks = 0; ks < KT; ks += 16) {
            const int kh = (k0 + ks) >> 1;
            unsigned a0 = zh0[kh + cg];
            unsigned a1 = zh1[kh + cg];
            unsigned a2 = zh0[kh + cg + 4];
            unsigned a3 = zh1[kh + cg + 4];
            const unsigned* wsb0 = buf + ((ks >> 1) + cg) * WS_STRIDE + g;
            const unsigned* wsb1 = wsb0 + 4 * WS_STRIDE;
            #pragma unroll
            for (int t = 0; t < 16; t++)
                mma_f16(acc[t], a0, a1, a2, a3, wsb0[t * 8], wsb1[t * 8]);
        }
    }
    #undef LOADREGS
    #undef STOREREGS

    const int chunk = blockIdx.x;
    float m0 = -INFINITY, m1 = -INFINITY;
    #pragma unroll
    for (int t = 0; t < 16; t++) {
        int n = t * 8 + 2 * cg;
        bool ok0 = (v0 + n) < V;
        bool ok1 = (v0 + n + 1) < V;
        float bv0 = ok0 ? bvoc[v0 + n] : 0.f;
        float bv1 = ok1 ? bvoc[v0 + n + 1] : 0.f;
        acc[t][0] = ok0 ? acc[t][0] + bv0 : -INFINITY;
        acc[t][1] = ok1 ? acc[t][1] + bv1 : -INFINITY;
        acc[t][2] = ok0 ? acc[t][2] + bv0 : -INFINITY;
        acc[t][3] = ok1 ? acc[t][3] + bv1 : -INFINITY;
        m0 = fmaxf(m0, fmaxf(acc[t][0], acc[t][1]));
        m1 = fmaxf(m1, fmaxf(acc[t][2], acc[t][3]));
    }
    #pragma unroll
    for (int o = 1; o <= 2; o <<= 1) {
        m0 = fmaxf(m0, __shfl_xor_sync(0xffffffffu, m0, o));
        m1 = fmaxf(m1, __shfl_xor_sync(0xffffffffu, m1, o));
    }
    float s0 = 0.f, s1 = 0.f;
    #pragma unroll
    for (int t = 0; t < 16; t++) {
        s0 += __expf(acc[t][0] - m0) + __expf(acc[t][1] - m0);
        s1 += __expf(acc[t][2] - m1) + __expf(acc[t][3] - m1);
    }
    #pragma unroll
    for (int o = 1; o <= 2; o <<= 1) {
        s0 += __shfl_xor_sync(0xffffffffu, s0, o);
        s1 += __shfl_xor_sync(0xffffffffu, s1, o);
    }
    if (cg == 0) {
        int r0 = b0 + w * 16 + g;
        g_pmax[r0 * NCHUNK + chunk] = m0;
        g_psum[r0 * NCHUNK + chunk] = s0;
        g_pmax[(r0 + 8) * NCHUNK + chunk] = m1;
        g_psum[(r0 + 8) * NCHUNK + chunk] = s1;
    }
}

// ---------------- kernel 3: logsumexp combine + context gather + fused mean ----
__global__ void __launch_bounds__(128) finalize_rows(
    const float* __restrict__ Wv, const float* __restrict__ bvoc,
    const int* __restrict__ context_ids, float* __restrict__ out)
{
    __shared__ long long blk_s[4];

    const int warp = threadIdx.x >> 5;
    const int lane = threadIdx.x & 31;
    const int b = blockIdx.x * 4 + warp;

    float m = -INFINITY, s = 0.f;
    for (int ch = lane; ch < NCHUNK; ch += 32) {
        float m2 = g_pmax[b * NCHUNK + ch];
        float s2 = g_psum[b * NCHUNK + ch];
        if (m2 > m) { s = s * __expf(m - m2) + s2; m = m2; }
        else        { s += s2 * __expf(m2 - m); }
    }
    #pragma unroll
    for (int o = 16; o; o >>= 1) {
        float m2 = __shfl_xor_sync(0xffffffffu, m, o);
        float s2 = __shfl_xor_sync(0xffffffffu, s, o);
        if (m2 > m) { s = s * __expf(m - m2) + s2; m = m2; }
        else        { s += s2 * __expf(m2 - m); }
    }
    float lse = m + logf(s);

    float zr[4];
    #pragma unroll
    for (int t = 0; t < 4; t++) zr[t] = g_z[b * D + lane + 32 * t];

    float rec = 0.f;
    #pragma unroll
    for (int c = 0; c < C; c++) {
        int v = context_ids[b * C + c];
        float p = 0.f;
        #pragma unroll
        for (int t = 0; t < 4; t++)
            p = fmaf(zr[t], Wv[(lane + 32 * t) * V + v], p);
        #pragma unroll
        for (int o = 16; o; o >>= 1) p += __shfl_xor_sync(0xffffffffu, p, o);
        rec += p + bvoc[v] - lse;
    }

    if (lane == 0) {
        float val = rec - g_kl[b];
        blk_s[warp] = __double2ll_rn((double)val * 4294967296.0);
    }
    __syncthreads();
    if (threadIdx.x == 0) {
        long long bs = blk_s[0] + blk_s[1] + blk_s[2] + blk_s[3];
        atomicAdd((unsigned long long*)&g_acc, (unsigned long long)bs);
        __threadfence();
        unsigned int done = atomicAdd(&g_done, 1u);
        if (done == FIN_BLOCKS - 1) {
            long long tot = *(volatile long long*)&g_acc;
            out[0] = (float)((double)tot * (1.0 / 4294967296.0) * (1.0 / (double)B));
        }
    }
}

// ---------------- launch ----------------
extern "C" void kernel_launch(void* const* d_in, const int* in_sizes, int n_in,
                              void* d_out, int out_size)
{
    const int*   center_id   = (const int*)d_in[0];
    const int*   context_ids = (const int*)d_in[1];
    const float* epsilon     = (const float*)d_in[2];
    const float* emb         = (const float*)d_in[3];
    const float* prior_means = (const float*)d_in[4];
    const float* prior_vars  = (const float*)d_in[5];
    const float* W_enc       = (const float*)d_in[6];
    const float* b_enc       = (const float*)d_in[7];
    const float* W_mean      = (const float*)d_in[8];
    const float* b_mean      = (const float*)d_in[9];
    const float* W_var       = (const float*)d_in[10];
    const float* b_var       = (const float*)d_in[11];
    const float* W_vocab     = (const float*)d_in[12];
    const float* b_vocab     = (const float*)d_in[13];
    float* out = (float*)d_out;

    encoder_kernel<<<B / NB, 256>>>(center_id, context_ids, epsilon, emb,
                                    prior_means, prior_vars,
                                    W_enc, b_enc, W_mean, b_mean, W_var, b_var);

    dim3 grid2(NCHUNK, B / M_CTA);
    vocab_kernel<<<grid2, 256>>>(W_vocab, b_vocab);

    finalize_rows<<<FIN_BLOCKS, 128>>>(W_vocab, b_vocab, context_ids, out);
}